// round 16
// baseline (speedup 1.0000x reference)
#include <cuda_runtime.h>
#include <cuda_fp16.h>
#include <mma.h>
#include <math.h>
#include <stdint.h>

using namespace nvcuda;

#define NB 4
#define NT 4096
#define ND 256

#define BM 128
#define BN 128
#define BK 32
#define NTILES_M (NT / BM)      // 32
#define N_ITEMS 1024            // 32 ti * 4 b * 2 nh * 4 seg (some skipped)

#define LDA 40                  // smem row stride (fp16 elems): 32 + 8 pad = 80B
#define LDE 136                 // epilogue f32 row stride
#define LDR 133                 // rowsum tile stride (f32): gcd(133,32)=1 -> conflict-free cols

#define ASCALE 2048.0f          // 2^11: lift fp16 operands out of subnormals
#define INV_ASCALE (1.0f / 2048.0f)

__device__ __align__(16) float g_dinv[NB * NT];
__device__ __align__(16) float g_psum[NB * 32 * NT];   // [b][slot][t], each slot written once
__device__ unsigned int g_rmax[NB * NT];               // zero-init; atomicMax idempotent
__device__ int g_ctr;
__device__ __align__(16) __half g_Ah[(size_t)NB * NT * NT];    // SG*dinv*A*dinv*2^11, masked
__device__ __align__(16) __half g_Kth[(size_t)NB * ND * NT];   // [b][d][s]
__device__ __align__(16) float g_part[(size_t)N_ITEMS * BM * BN];  // 64MB partials

#define SG 0.70710678118654752440f
#define GATE_TH 7.0710678118654752e-10f          // 1e-9 * sqrt(0.5)

#define TILE_B  (128 * LDA * 2)                  // 10240 bytes (128 rows x 80B)
#define STAGE_B (2 * TILE_B)                     // 20480 (A + B)
#define NSTG 4
#define SM_TOTAL (NSTG * STAGE_B)                // 81920 (> epilogue 69632)
#define SM_ROWSUM (128 * LDR * 4)                // 68096

static __device__ __forceinline__ uint32_t smem_u32(const void* p) {
    uint32_t a;
    asm("{ .reg .u64 t; cvta.to.shared.u64 t, %1; cvt.u32.u64 %0, t; }" : "=r"(a) : "l"(p));
    return a;
}
static __device__ __forceinline__ void cp16(uint32_t dst, const void* src) {
    asm volatile("cp.async.cg.shared.global [%0], [%1], 16;" :: "r"(dst), "l"(src));
}

// ---------------------------------------------------------------------------
__global__ void reset_kernel() { if (threadIdx.x == 0) g_ctr = 0; }

// ---------------------------------------------------------------------------
// Kernel 1a: symmetric rowsum pass 1. One CTA per lower tile (ci <= ti).
// Stages the 128x128 f32 tile in smem, emits:
//   ci < ti : rowsum(r) -> psum[b][ci][t0+r],  colsum(c) -> psum[b][ti][s0+c]
//   ci == ti: full rowsum(r) -> psum[b][ti][t0+r]
// Each (slot, row) is written exactly once across the grid -> deterministic.
// ---------------------------------------------------------------------------
__global__ __launch_bounds__(256) void rowsum1_kernel(const float* __restrict__ A)
{
    extern __shared__ float rt[];     // [128][LDR]
    int ci = blockIdx.x, ti = blockIdx.y, b = blockIdx.z;
    if (ci > ti) return;
    int t0 = ti * 128, s0 = ci * 128;
    int tid = threadIdx.x;

    const float* Ab = A + (size_t)b * NT * NT;
    // load tile (coalesced float4)
    #pragma unroll
    for (int q = 0; q < 16; q++) {
        int f4 = tid + q * 256;            // 4096 float4s
        int r = f4 >> 5, c4 = (f4 & 31) * 4;
        float4 v = *reinterpret_cast<const float4*>(Ab + (size_t)(t0 + r) * NT + s0 + c4);
        float* dst = rt + r * LDR + c4;
        dst[0] = v.x; dst[1] = v.y; dst[2] = v.z; dst[3] = v.w;
    }
    __syncthreads();

    int r = tid >> 1, h = tid & 1;
    // row sums
    {
        float s = 0.f;
        const float* row = rt + r * LDR + h * 64;
        #pragma unroll
        for (int j = 0; j < 64; j++) s += row[j];
        s += __shfl_xor_sync(0xffffffffu, s, 1);
        if (h == 0) g_psum[(b * 32 + ci) * NT + t0 + r] = s;   // slot ci (== ti when diag)
    }
    // col sums (off-diagonal tiles only)
    if (ci < ti) {
        int c = r;
        float s = 0.f;
        const float* col = rt + h * 64 * LDR + c;
        #pragma unroll
        for (int j = 0; j < 64; j++) s += col[j * LDR];
        s += __shfl_xor_sync(0xffffffffu, s, 1);
        if (h == 0) g_psum[(b * 32 + ti) * NT + s0 + c] = s;
    }
}

// ---------------------------------------------------------------------------
// Kernel 1b: reduce 32 slots per row (fixed order) -> dinv
// ---------------------------------------------------------------------------
__global__ __launch_bounds__(256) void rowsum2_kernel()
{
    int idx = blockIdx.x * 256 + threadIdx.x;     // 0 .. NB*NT-1
    int b = idx >> 12, t = idx & (NT - 1);
    const float* p = g_psum + b * 32 * NT + t;
    float s = 0.f;
    #pragma unroll
    for (int k = 0; k < 32; k++) s += p[k * NT];
    g_dinv[idx] = 1.0f / sqrtf(s + 1e-6f);
}

// ---------------------------------------------------------------------------
// Kernel 2: K[b][s][d] -> Kth[b][d][s] fp16 transpose
// ---------------------------------------------------------------------------
__global__ __launch_bounds__(256) void kt_kernel(const float* __restrict__ K)
{
    __shared__ float tile[32][33];
    int s0 = blockIdx.x * 32, d0 = blockIdx.y * 32, b = blockIdx.z;
    const float* Kb = K + (size_t)b * NT * ND;
    int tid = threadIdx.x;
    #pragma unroll
    for (int q = 0; q < 4; q++) {
        int idx = tid + q * 256;
        int r = idx >> 5, c = idx & 31;
        tile[r][c] = Kb[(size_t)(s0 + r) * ND + d0 + c];
    }
    __syncthreads();
    #pragma unroll
    for (int q = 0; q < 4; q++) {
        int idx = tid + q * 256;
        int dr = idx >> 5, sc = idx & 31;
        g_Kth[(size_t)b * ND * NT + (size_t)(d0 + dr) * NT + s0 + sc] =
            __float2half_rn(tile[sc][dr]);
    }
}

// ---------------------------------------------------------------------------
// Kernel 3: convert lower-triangle A -> scaled/masked fp16 (x2^11) + rmax.
// ---------------------------------------------------------------------------
__global__ __launch_bounds__(256) void convert_kernel(const float* __restrict__ A)
{
    int ci = blockIdx.x, ti = blockIdx.y, b = blockIdx.z;
    if (ci > ti) return;
    int t0 = ti * 128, s0 = ci * 128;
    int tid = threadIdx.x;
    int r = tid >> 1;
    int h = tid & 1;
    int t = t0 + r;

    const float* dinv = g_dinv + b * NT;
    float dt = SG * __ldg(dinv + t);
    const float* Arow = A + (size_t)b * NT * NT + (size_t)t * NT + s0;
    __half* Adst = g_Ah + ((size_t)b * NT + t) * NT + s0;

    bool diag = (ci == ti);
    float rmax = 0.f;
    #pragma unroll
    for (int q = 0; q < 8; q++) {
        int e0 = q * 16 + h * 8;
        float4 a0 = *reinterpret_cast<const float4*>(Arow + e0);
        float4 a1 = *reinterpret_cast<const float4*>(Arow + e0 + 4);
        float4 d0 = __ldg(reinterpret_cast<const float4*>(dinv + s0 + e0));
        float4 d1 = __ldg(reinterpret_cast<const float4*>(dinv + s0 + e0 + 4));
        float v[8] = { dt * a0.x * d0.x, dt * a0.y * d0.y, dt * a0.z * d0.z, dt * a0.w * d0.w,
                       dt * a1.x * d1.x, dt * a1.y * d1.y, dt * a1.z * d1.z, dt * a1.w * d1.w };
        int sbase = s0 + e0;
        #pragma unroll
        for (int e = 0; e < 8; e++) {
            if (diag && (sbase + e > t)) v[e] = 0.f;
            rmax = fmaxf(rmax, fabsf(v[e]));
        }
        uint32_t hw[4];
        #pragma unroll
        for (int p = 0; p < 4; p++) {
            __half2 hp = __floats2half2_rn(v[2 * p] * ASCALE, v[2 * p + 1] * ASCALE);
            hw[p] = *reinterpret_cast<uint32_t*>(&hp);
        }
        *reinterpret_cast<uint4*>(Adst + e0) = make_uint4(hw[0], hw[1], hw[2], hw[3]);
    }
    rmax = fmaxf(rmax, __shfl_xor_sync(0xffffffffu, rmax, 1));
    if (h == 0)
        atomicMax(&g_rmax[b * NT + t], __float_as_uint(rmax));
}

// ---------------------------------------------------------------------------
// Kernel 4: persistent split-K fp16 WMMA GEMM, 4-stage cp.async pipeline
// (window of 3 groups in flight hides chunk DRAM latency).
// ---------------------------------------------------------------------------
__global__ __launch_bounds__(256, 2) void causal_mm_wmma()
{
    extern __shared__ char smem[];
    uint32_t sb = smem_u32(smem);
    __shared__ int s_item;

    int tid = threadIdx.x, wid = tid >> 5;
    int wm = wid & 3;
    int wn = wid >> 2;
    int lr = tid >> 1;
    int lb = (tid & 1) * 32;

    while (true) {
        if (tid == 0) s_item = atomicAdd(&g_ctr, 1);
        __syncthreads();
        int item = s_item;
        if (item >= N_ITEMS) break;

        int ti  = NTILES_M - 1 - (item >> 5);   // big tiles first
        int rem = item & 31;
        int b   = rem >> 3;
        int nh  = (rem >> 2) & 1;
        int seg = rem & 3;
        int nK  = 4 * (ti + 1);
        int ns  = (ti + 8) >> 3;                // ceil((ti+1)/8)
        if (seg >= ns) continue;
        int c0 = seg * 32;
        int c1 = min(c0 + 32, nK);

        int t0  = ti * BM;
        int cn0 = nh * BN;
        const __half* Ag = g_Ah + ((size_t)b * NT + t0) * NT;
        const __half* Bg = g_Kth + ((size_t)b * ND + cn0) * NT;

        wmma::fragment<wmma::accumulator, 16, 16, 16, float> facc[2][4];
        #pragma unroll
        for (int i = 0; i < 2; i++)
            #pragma unroll
            for (int j = 0; j < 4; j++) wmma::fill_fragment(facc[i][j], 0.0f);

        auto load_stage = [&](int kk, int stage) {
            uint32_t s_base = sb + stage * STAGE_B + lr * 80 + lb;
            size_t goff = (size_t)lr * NT + (size_t)kk * BK;
            const char* srcA = reinterpret_cast<const char*>(Ag + goff) + lb;
            const char* srcB = reinterpret_cast<const char*>(Bg + goff) + lb;
            #pragma unroll
            for (int j = 0; j < 2; j++) {
                cp16(s_base + j * 16, srcA + j * 16);
                cp16(s_base + TILE_B + j * 16, srcB + j * 16);
            }
            asm volatile("cp.async.commit_group;");
        };

        // prologue: up to 3 groups in flight
        load_stage(c0, 0);
        if (c0 + 1 < c1) load_stage(c0 + 1, 1);
        if (c0 + 2 < c1) load_stage(c0 + 2, 2);

        for (int kk = c0; kk < c1; kk++) {
            int idx = kk - c0;
            int cur = idx & (NSTG - 1);
            int inflight_after = min(c1 - 1, kk + 2) - kk;   // groups newer than kk
            if (inflight_after == 2)      asm volatile("cp.async.wait_group 2;" ::: "memory");
            else if (inflight_after == 1) asm volatile("cp.async.wait_group 1;" ::: "memory");
            else                          asm volatile("cp.async.wait_group 0;" ::: "memory");
            __syncthreads();               // stage cur ready AND compute of kk-1 done
            if (kk + 3 < c1) load_stage(kk + 3, (idx + 3) & (NSTG - 1));

            const __half* As = reinterpret_cast<const __half*>(smem + cur * STAGE_B);
            const __half* Bs = reinterpret_cast<const __half*>(smem + cur * STAGE_B + TILE_B);

            #pragma unroll
            for (int ks = 0; ks < 2; ks++) {
                wmma::fragment<wmma::matrix_a, 16, 16, 16, __half, wmma::row_major> fa[2];
                #pragma unroll
                for (int i = 0; i < 2; i++)
                    wmma::load_matrix_sync(fa[i], As + (wm * 32 + i * 16) * LDA + ks * 16, LDA);
                #pragma unroll
                for (int j = 0; j < 4; j++) {
                    wmma::fragment<wmma::matrix_b, 16, 16, 16, __half, wmma::col_major> fb;
                    wmma::load_matrix_sync(fb, Bs + (wn * 64 + j * 16) * LDA + ks * 16, LDA);
                    #pragma unroll
                    for (int i = 0; i < 2; i++)
                        wmma::mma_sync(facc[i][j], fa[i], fb, facc[i][j]);
                }
            }
        }

        __syncthreads();
        float* Es = reinterpret_cast<float*>(smem);
        #pragma unroll
        for (int i = 0; i < 2; i++)
            #pragma unroll
            for (int j = 0; j < 4; j++)
                wmma::store_matrix_sync(Es + (wm * 32 + i * 16) * LDE + wn * 64 + j * 16,
                                        facc[i][j], LDE, wmma::mem_row_major);
        __syncthreads();

        {   // write raw partial tile (gate + descale applied in reduce)
            int r = tid >> 1;
            int ch0 = (tid & 1) * 64;
            float* Prow = g_part + (size_t)item * (BM * BN) + r * BN + ch0;
            const float* Erow = Es + r * LDE + ch0;
            #pragma unroll
            for (int q = 0; q < 16; q++)
                *reinterpret_cast<float4*>(Prow + q * 4) =
                    *reinterpret_cast<const float4*>(Erow + q * 4);
        }
        // loop-top __syncthreads orders Es reads before next item's cp.async
    }
}

// ---------------------------------------------------------------------------
// Kernel 5: reduce partials over segs, apply gate + 2^-11 descale, write out.
// ---------------------------------------------------------------------------
__global__ __launch_bounds__(256) void reduce_kernel(float* __restrict__ out)
{
    int ti = blockIdx.x;
    int z  = blockIdx.y;
    int b  = z >> 1, nh = z & 1;
    int ns = (ti + 8) >> 3;
    int tid = threadIdx.x;
    int r  = tid >> 1;
    int ch = (tid & 1) * 64;
    int t  = ti * BM + r;

    int item0 = (NTILES_M - 1 - ti) * 32 + b * 8 + nh * 4;
    const float* base = g_part + (size_t)item0 * (BM * BN) + r * BN + ch;

    float4 acc[16];
    #pragma unroll
    for (int q = 0; q < 16; q++)
        acc[q] = *reinterpret_cast<const float4*>(base + q * 4);
    for (int s = 1; s < ns; s++) {
        const float* p = base + (size_t)s * (BM * BN);
        #pragma unroll
        for (int q = 0; q < 16; q++) {
            float4 v = *reinterpret_cast<const float4*>(p + q * 4);
            acc[q].x += v.x; acc[q].y += v.y; acc[q].z += v.z; acc[q].w += v.w;
        }
    }

    float rm = __uint_as_float(g_rmax[b * NT + t]);
    float f  = (rm > GATE_TH) ? INV_ASCALE : 0.0f;
    float* Orow = out + ((size_t)b * NT + t) * ND + nh * BN + ch;
    #pragma unroll
    for (int q = 0; q < 16; q++) {
        float4 o = make_float4(acc[q].x * f, acc[q].y * f, acc[q].z * f, acc[q].w * f);
        *reinterpret_cast<float4*>(Orow + q * 4) = o;
    }
}

// ---------------------------------------------------------------------------
extern "C" void kernel_launch(void* const* d_in, const int* in_sizes, int n_in,
                              void* d_out, int out_size)
{
    const float* A = (const float*)d_in[0];   // (4, 4096, 4096) fp32
    const float* K = (const float*)d_in[1];   // (4, 4096, 256)  fp32
    float* out = (float*)d_out;               // (4, 4096, 256)  fp32

    cudaFuncSetAttribute(causal_mm_wmma, cudaFuncAttributeMaxDynamicSharedMemorySize, SM_TOTAL);
    cudaFuncSetAttribute(rowsum1_kernel, cudaFuncAttributeMaxDynamicSharedMemorySize, SM_ROWSUM);

    reset_kernel<<<1, 32>>>();

    dim3 gr1(NTILES_M, NTILES_M, NB);
    rowsum1_kernel<<<gr1, 256, SM_ROWSUM>>>(A);
    rowsum2_kernel<<<NB * NT / 256, 256>>>();

    dim3 gk(NT / 32, ND / 32, NB);
    kt_kernel<<<gk, 256>>>(K);

    dim3 gc(NTILES_M, NTILES_M, NB);
    convert_kernel<<<gc, 256>>>(A);

    causal_mm_wmma<<<296, 256, SM_TOTAL>>>();

    dim3 grd(NTILES_M, 8);
    reduce_kernel<<<grd, 256>>>(out);
}

// round 17
// speedup vs baseline: 1.0624x; 1.0624x over previous
#include <cuda_runtime.h>
#include <cuda_fp16.h>
#include <mma.h>
#include <math.h>
#include <stdint.h>

using namespace nvcuda;

#define NB 4
#define NT 4096
#define ND 256

#define BM 128
#define BN 128
#define BK 32
#define NTILES_M (NT / BM)      // 32
#define N_ITEMS 1024            // 32 ti * 4 b * 2 nh * 4 seg (some skipped)

#define LDA 40                  // smem row stride (fp16 elems): 32 + 8 pad = 80B
#define LDE 136                 // epilogue f32 row stride
#define LDR 133                 // rowsum tile stride (f32): gcd(133,32)=1 -> conflict-free cols

#define ASCALE 2048.0f          // 2^11: lift fp16 operands out of subnormals
#define INV_ASCALE (1.0f / 2048.0f)

__device__ __align__(16) float g_dinv[NB * NT];
__device__ __align__(16) float g_psum[NB * 32 * NT];   // [b][slot][t], each slot written once
__device__ unsigned int g_rmax[NB * NT];               // zero-init; atomicMax idempotent
__device__ int g_ctr;
__device__ __align__(16) __half g_Ah[(size_t)NB * NT * NT];    // SG*dinv*A*dinv*2^11, masked
__device__ __align__(16) __half g_Kth[(size_t)NB * ND * NT];   // [b][d][s]
__device__ __align__(16) float g_part[(size_t)N_ITEMS * BM * BN];  // 64MB partials

#define SG 0.70710678118654752440f
#define GATE_TH 7.0710678118654752e-10f          // 1e-9 * sqrt(0.5)

#define TILE_B  (128 * LDA * 2)                  // 10240 bytes (128 rows x 80B)
#define STAGE_B (2 * TILE_B)                     // 20480 (A + B)
#define NSTG 4
#define SM_TOTAL (NSTG * STAGE_B)                // 81920 (> epilogue 69632)
#define SM_ROWSUM (128 * LDR * 4)                // 68096

static __device__ __forceinline__ uint32_t smem_u32(const void* p) {
    uint32_t a;
    asm("{ .reg .u64 t; cvta.to.shared.u64 t, %1; cvt.u32.u64 %0, t; }" : "=r"(a) : "l"(p));
    return a;
}
static __device__ __forceinline__ void cp16(uint32_t dst, const void* src) {
    asm volatile("cp.async.cg.shared.global [%0], [%1], 16;" :: "r"(dst), "l"(src));
}

// ---------------------------------------------------------------------------
// Kernel 1a: symmetric rowsum pass 1. One CTA per lower tile (ci <= ti).
//   ci < ti : rowsum(r) -> psum[b][ci][t0+r],  colsum(c) -> psum[b][ti][s0+c]
//   ci == ti: full rowsum(r) -> psum[b][ti][t0+r]
// Each (slot, row) written exactly once across the grid -> deterministic.
// ---------------------------------------------------------------------------
__global__ __launch_bounds__(256) void rowsum1_kernel(const float* __restrict__ A)
{
    extern __shared__ float rt[];     // [128][LDR]
    int ci = blockIdx.x, ti = blockIdx.y, b = blockIdx.z;
    if (ci > ti) return;
    int t0 = ti * 128, s0 = ci * 128;
    int tid = threadIdx.x;

    const float* Ab = A + (size_t)b * NT * NT;
    #pragma unroll
    for (int q = 0; q < 16; q++) {
        int f4 = tid + q * 256;            // 4096 float4s
        int r = f4 >> 5, c4 = (f4 & 31) * 4;
        float4 v = *reinterpret_cast<const float4*>(Ab + (size_t)(t0 + r) * NT + s0 + c4);
        float* dst = rt + r * LDR + c4;
        dst[0] = v.x; dst[1] = v.y; dst[2] = v.z; dst[3] = v.w;
    }
    __syncthreads();

    int r = tid >> 1, h = tid & 1;
    {
        float s = 0.f;
        const float* row = rt + r * LDR + h * 64;
        #pragma unroll
        for (int j = 0; j < 64; j++) s += row[j];
        s += __shfl_xor_sync(0xffffffffu, s, 1);
        if (h == 0) g_psum[(b * 32 + ci) * NT + t0 + r] = s;
    }
    if (ci < ti) {
        int c = r;
        float s = 0.f;
        const float* col = rt + h * 64 * LDR + c;
        #pragma unroll
        for (int j = 0; j < 64; j++) s += col[j * LDR];
        s += __shfl_xor_sync(0xffffffffu, s, 1);
        if (h == 0) g_psum[(b * 32 + ti) * NT + s0 + c] = s;
    }
}

// ---------------------------------------------------------------------------
// Kernel 1b: reduce 32 slots per row (fixed order) -> dinv.
// Also resets the mm work-queue counter (runs before mm every replay).
// ---------------------------------------------------------------------------
__global__ __launch_bounds__(256) void rowsum2_kernel()
{
    if (blockIdx.x == 0 && threadIdx.x == 0) g_ctr = 0;
    int idx = blockIdx.x * 256 + threadIdx.x;     // 0 .. NB*NT-1
    int b = idx >> 12, t = idx & (NT - 1);
    const float* p = g_psum + b * 32 * NT + t;
    float s = 0.f;
    #pragma unroll
    for (int k = 0; k < 32; k++) s += p[k * NT];
    g_dinv[idx] = 1.0f / sqrtf(s + 1e-6f);
}

// ---------------------------------------------------------------------------
// Kernel 2: K[b][s][d] -> Kth[b][d][s] fp16 transpose
// ---------------------------------------------------------------------------
__global__ __launch_bounds__(256) void kt_kernel(const float* __restrict__ K)
{
    __shared__ float tile[32][33];
    int s0 = blockIdx.x * 32, d0 = blockIdx.y * 32, b = blockIdx.z;
    const float* Kb = K + (size_t)b * NT * ND;
    int tid = threadIdx.x;
    #pragma unroll
    for (int q = 0; q < 4; q++) {
        int idx = tid + q * 256;
        int r = idx >> 5, c = idx & 31;
        tile[r][c] = Kb[(size_t)(s0 + r) * ND + d0 + c];
    }
    __syncthreads();
    #pragma unroll
    for (int q = 0; q < 4; q++) {
        int idx = tid + q * 256;
        int dr = idx >> 5, sc = idx & 31;
        g_Kth[(size_t)b * ND * NT + (size_t)(d0 + dr) * NT + s0 + sc] =
            __float2half_rn(tile[sc][dr]);
    }
}

// ---------------------------------------------------------------------------
// Kernel 3: convert lower-triangle A -> scaled/masked fp16 (x2^11) + rmax.
// ---------------------------------------------------------------------------
__global__ __launch_bounds__(256) void convert_kernel(const float* __restrict__ A)
{
    int ci = blockIdx.x, ti = blockIdx.y, b = blockIdx.z;
    if (ci > ti) return;
    int t0 = ti * 128, s0 = ci * 128;
    int tid = threadIdx.x;
    int r = tid >> 1;
    int h = tid & 1;
    int t = t0 + r;

    const float* dinv = g_dinv + b * NT;
    float dt = SG * __ldg(dinv + t);
    const float* Arow = A + (size_t)b * NT * NT + (size_t)t * NT + s0;
    __half* Adst = g_Ah + ((size_t)b * NT + t) * NT + s0;

    bool diag = (ci == ti);
    float rmax = 0.f;
    #pragma unroll
    for (int q = 0; q < 8; q++) {
        int e0 = q * 16 + h * 8;
        float4 a0 = *reinterpret_cast<const float4*>(Arow + e0);
        float4 a1 = *reinterpret_cast<const float4*>(Arow + e0 + 4);
        float4 d0 = __ldg(reinterpret_cast<const float4*>(dinv + s0 + e0));
        float4 d1 = __ldg(reinterpret_cast<const float4*>(dinv + s0 + e0 + 4));
        float v[8] = { dt * a0.x * d0.x, dt * a0.y * d0.y, dt * a0.z * d0.z, dt * a0.w * d0.w,
                       dt * a1.x * d1.x, dt * a1.y * d1.y, dt * a1.z * d1.z, dt * a1.w * d1.w };
        int sbase = s0 + e0;
        #pragma unroll
        for (int e = 0; e < 8; e++) {
            if (diag && (sbase + e > t)) v[e] = 0.f;
            rmax = fmaxf(rmax, fabsf(v[e]));
        }
        uint32_t hw[4];
        #pragma unroll
        for (int p = 0; p < 4; p++) {
            __half2 hp = __floats2half2_rn(v[2 * p] * ASCALE, v[2 * p + 1] * ASCALE);
            hw[p] = *reinterpret_cast<uint32_t*>(&hp);
        }
        *reinterpret_cast<uint4*>(Adst + e0) = make_uint4(hw[0], hw[1], hw[2], hw[3]);
    }
    rmax = fmaxf(rmax, __shfl_xor_sync(0xffffffffu, rmax, 1));
    if (h == 0)
        atomicMax(&g_rmax[b * NT + t], __float_as_uint(rmax));
}

// ---------------------------------------------------------------------------
// Kernel 4: persistent split-K fp16 WMMA GEMM, 4-stage cp.async pipeline.
// (unchanged from R16 — pinned at the legacy-HMMA issue floor)
// ---------------------------------------------------------------------------
__global__ __launch_bounds__(256, 2) void causal_mm_wmma()
{
    extern __shared__ char smem[];
    uint32_t sb = smem_u32(smem);
    __shared__ int s_item;

    int tid = threadIdx.x, wid = tid >> 5;
    int wm = wid & 3;
    int wn = wid >> 2;
    int lr = tid >> 1;
    int lb = (tid & 1) * 32;

    while (true) {
        if (tid == 0) s_item = atomicAdd(&g_ctr, 1);
        __syncthreads();
        int item = s_item;
        if (item >= N_ITEMS) break;

        int ti  = NTILES_M - 1 - (item >> 5);   // big tiles first
        int rem = item & 31;
        int b   = rem >> 3;
        int nh  = (rem >> 2) & 1;
        int seg = rem & 3;
        int nK  = 4 * (ti + 1);
        int ns  = (ti + 8) >> 3;                // ceil((ti+1)/8)
        if (seg >= ns) continue;
        int c0 = seg * 32;
        int c1 = min(c0 + 32, nK);

        int t0  = ti * BM;
        int cn0 = nh * BN;
        const __half* Ag = g_Ah + ((size_t)b * NT + t0) * NT;
        const __half* Bg = g_Kth + ((size_t)b * ND + cn0) * NT;

        wmma::fragment<wmma::accumulator, 16, 16, 16, float> facc[2][4];
        #pragma unroll
        for (int i = 0; i < 2; i++)
            #pragma unroll
            for (int j = 0; j < 4; j++) wmma::fill_fragment(facc[i][j], 0.0f);

        auto load_stage = [&](int kk, int stage) {
            uint32_t s_base = sb + stage * STAGE_B + lr * 80 + lb;
            size_t goff = (size_t)lr * NT + (size_t)kk * BK;
            const char* srcA = reinterpret_cast<const char*>(Ag + goff) + lb;
            const char* srcB = reinterpret_cast<const char*>(Bg + goff) + lb;
            #pragma unroll
            for (int j = 0; j < 2; j++) {
                cp16(s_base + j * 16, srcA + j * 16);
                cp16(s_base + TILE_B + j * 16, srcB + j * 16);
            }
            asm volatile("cp.async.commit_group;");
        };

        load_stage(c0, 0);
        if (c0 + 1 < c1) load_stage(c0 + 1, 1);
        if (c0 + 2 < c1) load_stage(c0 + 2, 2);

        for (int kk = c0; kk < c1; kk++) {
            int idx = kk - c0;
            int cur = idx & (NSTG - 1);
            int inflight_after = min(c1 - 1, kk + 2) - kk;
            if (inflight_after == 2)      asm volatile("cp.async.wait_group 2;" ::: "memory");
            else if (inflight_after == 1) asm volatile("cp.async.wait_group 1;" ::: "memory");
            else                          asm volatile("cp.async.wait_group 0;" ::: "memory");
            __syncthreads();
            if (kk + 3 < c1) load_stage(kk + 3, (idx + 3) & (NSTG - 1));

            const __half* As = reinterpret_cast<const __half*>(smem + cur * STAGE_B);
            const __half* Bs = reinterpret_cast<const __half*>(smem + cur * STAGE_B + TILE_B);

            #pragma unroll
            for (int ks = 0; ks < 2; ks++) {
                wmma::fragment<wmma::matrix_a, 16, 16, 16, __half, wmma::row_major> fa[2];
                #pragma unroll
                for (int i = 0; i < 2; i++)
                    wmma::load_matrix_sync(fa[i], As + (wm * 32 + i * 16) * LDA + ks * 16, LDA);
                #pragma unroll
                for (int j = 0; j < 4; j++) {
                    wmma::fragment<wmma::matrix_b, 16, 16, 16, __half, wmma::col_major> fb;
                    wmma::load_matrix_sync(fb, Bs + (wn * 64 + j * 16) * LDA + ks * 16, LDA);
                    #pragma unroll
                    for (int i = 0; i < 2; i++)
                        wmma::mma_sync(facc[i][j], fa[i], fb, facc[i][j]);
                }
            }
        }

        __syncthreads();
        float* Es = reinterpret_cast<float*>(smem);
        #pragma unroll
        for (int i = 0; i < 2; i++)
            #pragma unroll
            for (int j = 0; j < 4; j++)
                wmma::store_matrix_sync(Es + (wm * 32 + i * 16) * LDE + wn * 64 + j * 16,
                                        facc[i][j], LDE, wmma::mem_row_major);
        __syncthreads();

        {
            int r = tid >> 1;
            int ch0 = (tid & 1) * 64;
            float* Prow = g_part + (size_t)item * (BM * BN) + r * BN + ch0;
            const float* Erow = Es + r * LDE + ch0;
            #pragma unroll
            for (int q = 0; q < 16; q++)
                *reinterpret_cast<float4*>(Prow + q * 4) =
                    *reinterpret_cast<const float4*>(Erow + q * 4);
        }
    }
}

// ---------------------------------------------------------------------------
// Kernel 5: reduce partials over segs, apply gate + 2^-11 descale, write out.
// 4x parallelism vs before: grid (128 rowblocks, 8), CTA covers 32 rows;
// 8 consecutive threads cover one row's 128B-contiguous 64B chunks.
// ---------------------------------------------------------------------------
__global__ __launch_bounds__(256) void reduce_kernel(float* __restrict__ out)
{
    int bx = blockIdx.x;                   // 0..127
    int ti = bx >> 2, rb = bx & 3;
    int z  = blockIdx.y;
    int b  = z >> 1, nh = z & 1;
    int ns = (ti + 8) >> 3;
    int tid = threadIdx.x;
    int r  = rb * 32 + (tid >> 3);         // row in 128-row tile
    int ch = (tid & 7) * 16;               // 16 floats = 64B
    int t  = ti * BM + r;

    int item0 = (NTILES_M - 1 - ti) * 32 + b * 8 + nh * 4;
    const float* base = g_part + (size_t)item0 * (BM * BN) + r * BN + ch;

    float4 acc[4];
    #pragma unroll
    for (int q = 0; q < 4; q++)
        acc[q] = *reinterpret_cast<const float4*>(base + q * 4);
    for (int s = 1; s < ns; s++) {
        const float* p = base + (size_t)s * (BM * BN);
        #pragma unroll
        for (int q = 0; q < 4; q++) {
            float4 v = *reinterpret_cast<const float4*>(p + q * 4);
            acc[q].x += v.x; acc[q].y += v.y; acc[q].z += v.z; acc[q].w += v.w;
        }
    }

    float rm = __uint_as_float(g_rmax[b * NT + t]);
    float f  = (rm > GATE_TH) ? INV_ASCALE : 0.0f;
    float* Orow = out + ((size_t)b * NT + t) * ND + nh * BN + ch;
    #pragma unroll
    for (int q = 0; q < 4; q++) {
        float4 o = make_float4(acc[q].x * f, acc[q].y * f, acc[q].z * f, acc[q].w * f);
        *reinterpret_cast<float4*>(Orow + q * 4) = o;
    }
}

// ---------------------------------------------------------------------------
extern "C" void kernel_launch(void* const* d_in, const int* in_sizes, int n_in,
                              void* d_out, int out_size)
{
    const float* A = (const float*)d_in[0];   // (4, 4096, 4096) fp32
    const float* K = (const float*)d_in[1];   // (4, 4096, 256)  fp32
    float* out = (float*)d_out;               // (4, 4096, 256)  fp32

    cudaFuncSetAttribute(causal_mm_wmma, cudaFuncAttributeMaxDynamicSharedMemorySize, SM_TOTAL);
    cudaFuncSetAttribute(rowsum1_kernel, cudaFuncAttributeMaxDynamicSharedMemorySize, SM_ROWSUM);

    dim3 gr1(NTILES_M, NTILES_M, NB);
    rowsum1_kernel<<<gr1, 256, SM_ROWSUM>>>(A);
    rowsum2_kernel<<<NB * NT / 256, 256>>>();   // also resets g_ctr

    dim3 gk(NT / 32, ND / 32, NB);
    kt_kernel<<<gk, 256>>>(K);

    dim3 gc(NTILES_M, NTILES_M, NB);
    convert_kernel<<<gc, 256>>>(A);

    causal_mm_wmma<<<296, 256, SM_TOTAL>>>();

    dim3 grd(NTILES_M * 4, 8);
    reduce_kernel<<<grd, 256>>>(out);
}